// round 4
// baseline (speedup 1.0000x reference)
#include <cuda_runtime.h>
#include <cuda_bf16.h>
#include <float.h>
#include <stdint.h>

// Problem constants (fixed: x[32,2048,512] fp32, codebook[1024,512] fp32)
#define C_DIM    512
#define K_CODES  1024
#define MAX_ROWS 65536

#define MARGIN 0.5f

// ---------------- device scratch (static, no runtime allocation) ----------
__device__ __nv_bfloat16 g_xb[(size_t)MAX_ROWS * C_DIM];   // 64 MB
__device__ __nv_bfloat16 g_cbb[(size_t)K_CODES * C_DIM];   // 1 MB
__device__ float g_cnorm[K_CODES];
__device__ float g_xnorm[MAX_ROWS];
__device__ int   g_idx[MAX_ROWS];
__device__ float g_partial[MAX_ROWS];
__device__ int   g_amb[MAX_ROWS];
__device__ int   g_amb_cnt;

// ---------------------------------------------------------------------------
// fp32 -> bf16 conversion (x), one float4 per thread.
// ---------------------------------------------------------------------------
__global__ __launch_bounds__(256) void convert_x_kernel(const float* __restrict__ x) {
    size_t i = (size_t)blockIdx.x * 256 + threadIdx.x;       // float4 index
    float4 v = ((const float4*)x)[i];
    __nv_bfloat162 p0 = __float22bfloat162_rn(make_float2(v.x, v.y));
    __nv_bfloat162 p1 = __float22bfloat162_rn(make_float2(v.z, v.w));
    uint2 pk;
    pk.x = *(const unsigned int*)&p0;
    pk.y = *(const unsigned int*)&p1;
    ((uint2*)g_xb)[i] = pk;
}

__global__ __launch_bounds__(256) void convert_cb_kernel(const float* __restrict__ cb) {
    size_t i = (size_t)blockIdx.x * 256 + threadIdx.x;
    if (blockIdx.x == 0 && threadIdx.x == 0) g_amb_cnt = 0;  // reset per launch
    float4 v = ((const float4*)cb)[i];
    __nv_bfloat162 p0 = __float22bfloat162_rn(make_float2(v.x, v.y));
    __nv_bfloat162 p1 = __float22bfloat162_rn(make_float2(v.z, v.w));
    uint2 pk;
    pk.x = *(const unsigned int*)&p0;
    pk.y = *(const unsigned int*)&p1;
    ((uint2*)g_cbb)[i] = pk;
}

// ---------------------------------------------------------------------------
// Warp row-norm (must stay bitwise-identical to the passing round-2 version).
// ---------------------------------------------------------------------------
__device__ __forceinline__ float warp_rownorm(const float* __restrict__ row, int lane) {
    float s = 0.f;
    #pragma unroll
    for (int i = 0; i < C_DIM / 32; i++) {
        float v = row[lane + 32 * i];
        s = fmaf(v, v, s);
    }
    s += __shfl_down_sync(0xFFFFFFFFu, s, 16);
    s += __shfl_down_sync(0xFFFFFFFFu, s, 8);
    s += __shfl_down_sync(0xFFFFFFFFu, s, 4);
    s += __shfl_down_sync(0xFFFFFFFFu, s, 2);
    s += __shfl_down_sync(0xFFFFFFFFu, s, 1);
    return s;
}

__global__ __launch_bounds__(256) void cnorm_kernel(const float* __restrict__ cb) {
    int code = blockIdx.x * 8 + (threadIdx.x >> 5);
    int lane = threadIdx.x & 31;
    float s = warp_rownorm(cb + (size_t)code * C_DIM, lane);
    if (lane == 0) g_cnorm[code] = s;
}

__global__ __launch_bounds__(256) void xnorm_kernel(const float* __restrict__ x) {
    int row = blockIdx.x * 8 + (threadIdx.x >> 5);
    int lane = threadIdx.x & 31;
    float s = warp_rownorm(x + (size_t)row * C_DIM, lane);
    if (lane == 0) g_xnorm[row] = s;
}

// ---------------------------------------------------------------------------
// Coarse bf16 tensor-core GEMM + top-2 tracking.
// CTA: 128 rows x 64 codes per n-tile, 16 n-tiles (all 1024 codes).
// 8 warps: warp_m in 0..3 (32-row strips), warp_n in 0..1 (32-code strips).
// Warp tile 32x32 = 2(m) x 4(n) m16n8k16 fragments.
// ---------------------------------------------------------------------------
#define CBM 128
#define CBN 64
#define PADK 40   // bf16 elements per smem row (32 data + 8 pad) -> conflict-free

__global__ __launch_bounds__(256, 2) void coarse_kernel() {
    __shared__ __nv_bfloat16 As[CBM * PADK];
    __shared__ __nv_bfloat16 Bs[CBN * PADK];
    __shared__ float cns[K_CODES];
    __shared__ float xns[CBM];
    __shared__ float rv1[CBM][2];
    __shared__ int   ri1[CBM][2];
    __shared__ float rv2[CBM][2];

    const int tid  = threadIdx.x;
    const int wid  = tid >> 5;
    const int lane = tid & 31;
    const int warp_m = wid & 3;       // row strip
    const int warp_n = wid >> 2;      // code strip
    const int rowBase = blockIdx.x * CBM;

    for (int i = tid; i < K_CODES; i += 256) cns[i] = g_cnorm[i];
    if (tid < CBM) xns[tid] = g_xnorm[rowBase + tid];
    __syncthreads();

    // per-thread row slots: s = tilem*2 + h -> row = warp_m*32 + tilem*16 + (lane>>2) + h*8
    float v1[4], v2[4];
    int   i1[4];
    float sx[4];
    #pragma unroll
    for (int s = 0; s < 4; s++) {
        v1[s] = FLT_MAX; v2[s] = FLT_MAX; i1[s] = 0;
        int row = warp_m * 32 + (s >> 1) * 16 + (lane >> 2) + (s & 1) * 8;
        sx[s] = xns[row];
    }

    // global->smem chunk mapping (16B chunks of 8 bf16)
    const int ra0 = tid >> 2,          qa0 = tid & 3;           // As chunk 0
    const int ra1 = (tid + 256) >> 2,  qa1 = (tid + 256) & 3;   // As chunk 1
    const int rb  = tid >> 2,          qb  = tid & 3;           // Bs chunk (tid<256 covers 64 rows*4)

    for (int nt = 0; nt < K_CODES / CBN; nt++) {
        float acc[2][4][4];
        #pragma unroll
        for (int tm = 0; tm < 2; tm++)
            #pragma unroll
            for (int tn = 0; tn < 4; tn++)
                #pragma unroll
                for (int r = 0; r < 4; r++) acc[tm][tn][r] = 0.f;

        for (int k0 = 0; k0 < C_DIM; k0 += 32) {
            __syncthreads();
            // load x tile: 128 rows x 32 halves
            {
                uint4 v = *(const uint4*)&g_xb[(size_t)(rowBase + ra0) * C_DIM + k0 + qa0 * 8];
                *(uint4*)&As[ra0 * PADK + qa0 * 8] = v;
                uint4 w = *(const uint4*)&g_xb[(size_t)(rowBase + ra1) * C_DIM + k0 + qa1 * 8];
                *(uint4*)&As[ra1 * PADK + qa1 * 8] = w;
            }
            // load codebook tile: 64 codes x 32 halves (tid 0..255 covers exactly 256 chunks)
            if (rb < CBN) {
                uint4 v = *(const uint4*)&g_cbb[(size_t)(nt * CBN + rb) * C_DIM + k0 + qb * 8];
                *(uint4*)&Bs[rb * PADK + qb * 8] = v;
            }
            __syncthreads();

            #pragma unroll
            for (int ks = 0; ks < 32; ks += 16) {
                const int kk = ks + (lane & 3) * 2;
                unsigned int a[2][4], b[4][2];
                #pragma unroll
                for (int tm = 0; tm < 2; tm++) {
                    int row0 = warp_m * 32 + tm * 16 + (lane >> 2);
                    a[tm][0] = *(const unsigned int*)&As[(row0    ) * PADK + kk    ];
                    a[tm][1] = *(const unsigned int*)&As[(row0 + 8) * PADK + kk    ];
                    a[tm][2] = *(const unsigned int*)&As[(row0    ) * PADK + kk + 8];
                    a[tm][3] = *(const unsigned int*)&As[(row0 + 8) * PADK + kk + 8];
                }
                #pragma unroll
                for (int tn = 0; tn < 4; tn++) {
                    int col0 = warp_n * 32 + tn * 8 + (lane >> 2);
                    b[tn][0] = *(const unsigned int*)&Bs[col0 * PADK + kk    ];
                    b[tn][1] = *(const unsigned int*)&Bs[col0 * PADK + kk + 8];
                }
                #pragma unroll
                for (int tm = 0; tm < 2; tm++)
                    #pragma unroll
                    for (int tn = 0; tn < 4; tn++) {
                        asm volatile(
                            "mma.sync.aligned.m16n8k16.row.col.f32.bf16.bf16.f32 "
                            "{%0,%1,%2,%3}, {%4,%5,%6,%7}, {%8,%9}, {%0,%1,%2,%3};\n"
                            : "+f"(acc[tm][tn][0]), "+f"(acc[tm][tn][1]),
                              "+f"(acc[tm][tn][2]), "+f"(acc[tm][tn][3])
                            : "r"(a[tm][0]), "r"(a[tm][1]), "r"(a[tm][2]), "r"(a[tm][3]),
                              "r"(b[tn][0]), "r"(b[tn][1]));
                    }
            }
        }

        // epilogue: distances + top-2 per owned row (codes ascending per thread)
        #pragma unroll
        for (int tn = 0; tn < 4; tn++) {
            #pragma unroll
            for (int tm = 0; tm < 2; tm++) {
                #pragma unroll
                for (int r = 0; r < 4; r++) {
                    int s    = tm * 2 + (r >> 1);
                    int code = nt * CBN + warp_n * 32 + tn * 8 + (lane & 3) * 2 + (r & 1);
                    float d = sx[s] - 2.0f * acc[tm][tn][r] + cns[code];
                    if (d < v1[s]) { v2[s] = v1[s]; v1[s] = d; i1[s] = code; }
                    else if (d < v2[s]) { v2[s] = d; }
                }
            }
        }
    }

    // merge across the 4 lanes (lane&3) sharing each row
    #pragma unroll
    for (int s = 0; s < 4; s++) {
        #pragma unroll
        for (int delta = 1; delta <= 2; delta <<= 1) {
            float ov1 = __shfl_xor_sync(0xFFFFFFFFu, v1[s], delta);
            int   oi1 = __shfl_xor_sync(0xFFFFFFFFu, i1[s], delta);
            float ov2 = __shfl_xor_sync(0xFFFFFFFFu, v2[s], delta);
            if (ov1 < v1[s] || (ov1 == v1[s] && oi1 < i1[s])) {
                v2[s] = fminf(v1[s], ov2); v1[s] = ov1; i1[s] = oi1;
            } else {
                v2[s] = fminf(v2[s], ov1);
            }
        }
    }

    if ((lane & 3) == 0) {
        #pragma unroll
        for (int s = 0; s < 4; s++) {
            int row = warp_m * 32 + (s >> 1) * 16 + (lane >> 2) + (s & 1) * 8;
            rv1[row][warp_n] = v1[s];
            ri1[row][warp_n] = i1[s];
            rv2[row][warp_n] = v2[s];
        }
    }
    __syncthreads();

    if (tid < CBM) {
        float a1 = rv1[tid][0], a2 = rv2[tid][0];
        int   ai = ri1[tid][0];
        float b1 = rv1[tid][1], b2 = rv2[tid][1];
        int   bi = ri1[tid][1];
        float m1, m2; int mi;
        if (b1 < a1 || (b1 == a1 && bi < ai)) { m1 = b1; mi = bi; m2 = fminf(a1, b2); }
        else                                  { m1 = a1; mi = ai; m2 = fminf(a2, b1); }
        g_idx[rowBase + tid] = mi;
        if (m2 - m1 < MARGIN) {
            int p = atomicAdd(&g_amb_cnt, 1);
            g_amb[p] = rowBase + tid;
        }
    }
}

// ---------------------------------------------------------------------------
// Exact fallback: for ambiguous rows, rescan ALL 1024 codes with the
// bitwise-identical round-2 arithmetic (sequential-k FMA, same rounding,
// lowest-index tie-break).
// ---------------------------------------------------------------------------
__global__ __launch_bounds__(256) void exact_kernel(
    const float* __restrict__ x, const float* __restrict__ cb)
{
    __shared__ float xs[C_DIM];
    __shared__ float sv[256];
    __shared__ int   si[256];
    __shared__ int   s_cnt;

    const int tid = threadIdx.x;
    if (tid == 0) s_cnt = g_amb_cnt;
    __syncthreads();
    const int cnt = s_cnt;

    for (int a = blockIdx.x; a < cnt; a += gridDim.x) {
        const int row = g_amb[a];
        __syncthreads();   // protect xs from previous iteration's readers
        for (int i = tid; i < C_DIM; i += 256) xs[i] = x[(size_t)row * C_DIM + i];
        __syncthreads();

        const float sx = g_xnorm[row];

        // 4 interleaved sequential FMA chains: codes tid, tid+256, tid+512, tid+768
        float dot[4] = {0.f, 0.f, 0.f, 0.f};
        const float* c0 = cb + (size_t)(tid      ) * C_DIM;
        const float* c1 = cb + (size_t)(tid + 256) * C_DIM;
        const float* c2 = cb + (size_t)(tid + 512) * C_DIM;
        const float* c3 = cb + (size_t)(tid + 768) * C_DIM;
        #pragma unroll 8
        for (int k = 0; k < C_DIM; k++) {
            float xv = xs[k];
            dot[0] = fmaf(xv, c0[k], dot[0]);
            dot[1] = fmaf(xv, c1[k], dot[1]);
            dot[2] = fmaf(xv, c2[k], dot[2]);
            dot[3] = fmaf(xv, c3[k], dot[3]);
        }

        float bv = FLT_MAX; int bi = 0;
        #pragma unroll
        for (int j = 0; j < 4; j++) {
            int code = tid + 256 * j;
            float t1 = __fmul_rn(2.0f, dot[j]);
            float t2 = __fsub_rn(sx, t1);
            float d  = __fadd_rn(t2, g_cnorm[code]);
            if (d < bv) { bv = d; bi = code; }
        }

        sv[tid] = bv; si[tid] = bi;
        __syncthreads();
        for (int s = 128; s > 0; s >>= 1) {
            if (tid < s) {
                float ov = sv[tid + s]; int oi = si[tid + s];
                if (ov < sv[tid] || (ov == sv[tid] && oi < si[tid])) {
                    sv[tid] = ov; si[tid] = oi;
                }
            }
            __syncthreads();
        }
        if (tid == 0) g_idx[row] = si[0];
    }
}

// ---------------------------------------------------------------------------
// Gather codebook rows into output + per-row squared-error partial.
// ---------------------------------------------------------------------------
__global__ __launch_bounds__(128) void gather_kernel(
    const float* __restrict__ x, const float* __restrict__ cb,
    float* __restrict__ out)
{
    int row = blockIdx.x;
    int t = threadIdx.x;
    int code = g_idx[row];

    const float4* xr = (const float4*)(x  + (size_t)row  * C_DIM);
    const float4* cr = (const float4*)(cb + (size_t)code * C_DIM);
    float4*       orr = (float4*)(out + (size_t)row * C_DIM);

    float4 xv = xr[t];
    float4 cv = cr[t];
    orr[t] = cv;

    float dx = xv.x - cv.x, dy = xv.y - cv.y, dz = xv.z - cv.z, dw = xv.w - cv.w;
    float s = dx * dx + dy * dy + dz * dz + dw * dw;

    #pragma unroll
    for (int o = 16; o > 0; o >>= 1) s += __shfl_xor_sync(0xFFFFFFFFu, s, o);

    __shared__ float ws[4];
    if ((t & 31) == 0) ws[t >> 5] = s;
    __syncthreads();
    if (t == 0) g_partial[row] = (ws[0] + ws[1]) + (ws[2] + ws[3]);
}

// ---------------------------------------------------------------------------
// Deterministic loss reduction.
// ---------------------------------------------------------------------------
__global__ __launch_bounds__(1024) void loss_kernel(
    float* __restrict__ out, int rows, long long out_size)
{
    int t = threadIdx.x;
    double s = 0.0;
    for (int i = t; i < rows; i += 1024) s += (double)g_partial[i];

    #pragma unroll
    for (int o = 16; o > 0; o >>= 1) s += __shfl_down_sync(0xFFFFFFFFu, s, o);

    __shared__ double ws[32];
    if ((t & 31) == 0) ws[t >> 5] = s;
    __syncthreads();
    if (t < 32) {
        double v = ws[t];
        #pragma unroll
        for (int o = 16; o > 0; o >>= 1) v += __shfl_down_sync(0xFFFFFFFFu, v, o);
        if (t == 0) {
            float loss = (float)(v / ((double)rows * (double)C_DIM));
            long long base = (long long)rows * C_DIM;
            for (long long i = base; i < out_size; i++) out[i] = loss;
        }
    }
}

// ---------------------------------------------------------------------------
extern "C" void kernel_launch(void* const* d_in, const int* in_sizes, int n_in,
                              void* d_out, int out_size)
{
    const float* x  = (const float*)d_in[0];
    const float* cb = (const float*)d_in[1];
    float* out = (float*)d_out;

    int rows = in_sizes[0] / C_DIM;   // 65536

    convert_x_kernel<<<(rows * (C_DIM / 4)) / 256, 256>>>(x);
    convert_cb_kernel<<<(K_CODES * (C_DIM / 4)) / 256, 256>>>(cb);
    cnorm_kernel<<<K_CODES / 8, 256>>>(cb);
    xnorm_kernel<<<rows / 8, 256>>>(x);
    coarse_kernel<<<rows / CBM, 256>>>();
    exact_kernel<<<1024, 256>>>(x, cb);
    gather_kernel<<<rows, 128>>>(x, cb, out);
    loss_kernel<<<1, 1024>>>(out, rows, (long long)out_size);
}